// round 13
// baseline (speedup 1.0000x reference)
#include <cuda_runtime.h>
#include <cuda_bf16.h>
#include <math.h>
#include <stdint.h>

#define BB   64
#define TMEL 2000
#define EE   512
#define MMI  80
#define PP   256
#define HH   1024
#define TD   1000
#define RR   (TD*BB)

#define GRU_NBLK 128
#define NRB      (RR/128)      // 500 row blocks

// ---------------- static device scratch (allocation-free rule) ----------------
__device__ float g_di [(size_t)RR*MMI];
__device__ float g_mem[(size_t)RR*EE];
__device__ float g_xa [(size_t)RR*PP];
__device__ float g_xb [(size_t)RR*PP];
__device__ float g_gi [(size_t)RR*3*HH];
__device__ float g_h1 [(size_t)RR*HH];
__device__ float g_h2 [(size_t)RR*HH];
__device__ float g_h3 [(size_t)RR*HH];
__device__ float g_d2 [(size_t)RR*HH];

// fragment-packed GEMM operands
__device__ __align__(16) uint4 g_Afrag[(size_t)NRB*48*1024];
__device__ __align__(16) uint4 g_Wfrag2[(size_t)24*48*1024];

// mma-fragment-packed recurrent weights + h ping-pong (verified)
__device__ __align__(16) uint4 g_wfrag[(size_t)128*8*8*3*32];
__device__ __align__(16) uint4 g_hfrag[(size_t)2*4*64*64];

__device__ unsigned g_barcnt;
__device__ unsigned g_bargen;

// ---------------- small prep kernels ----------------
__global__ void pool_kernel(const float* __restrict__ memorys)
{
    size_t total = (size_t)RR * EE;
    for (size_t i = (size_t)blockIdx.x*blockDim.x + threadIdx.x; i < total;
         i += (size_t)gridDim.x*blockDim.x) {
        int e = (int)(i % EE);
        int tb = (int)(i / EE);
        int b = tb & (BB-1);
        int t = tb >> 6;
        const float* src = memorys + ((size_t)b*TMEL + 2*t)*EE + e;
        g_mem[i] = 0.5f*(src[0] + src[EE]);
    }
}

__global__ void di_kernel(const float* __restrict__ dec)
{
    size_t total = (size_t)RR * MMI;
    for (size_t i = (size_t)blockIdx.x*blockDim.x + threadIdx.x; i < total;
         i += (size_t)gridDim.x*blockDim.x) {
        int m = (int)(i % MMI);
        int tb = (int)(i / MMI);
        int b = tb & (BB-1);
        int t = tb >> 6;
        g_di[i] = (t == 0) ? 0.0f : dec[((size_t)b*TMEL + (2*t-1))*MMI + m];
    }
}

__device__ __forceinline__ uint32_t pack_bf2(float lo, float hi)
{
    __nv_bfloat162 t = __floats2bfloat162_rn(lo, hi);
    return *(uint32_t*)&t;
}

// fused GEMM prep: A-frag pack (with optional multi-source add) + W-frag pack
// A = (A1 [+A1b] [+A1c]) concat A2, zero-padded to Kce
__global__ void prep_gemm(const float* __restrict__ A1,
                          const float* __restrict__ A1b,
                          const float* __restrict__ A1c, int K1,
                          const float* __restrict__ A2, int K2,
                          const float* __restrict__ W, int N, int nb, int nc)
{
    const int K = K1 + K2;
    const size_t aTotal = (size_t)NRB * nc * 512;
    const size_t wTotal = (size_t)nb * nc * 1024;
    for (size_t gidx = (size_t)blockIdx.x*blockDim.x + threadIdx.x;
         gidx < aTotal + wTotal;
         gidx += (size_t)gridDim.x*blockDim.x) {
        if (gidx < aTotal) {
            size_t idx = gidx;
            int lane = (int)(idx & 31);
            int mt   = (int)((idx >> 5) & 7);
            int ks   = (int)((idx >> 8) & 1);
            size_t r = idx >> 9;
            int ci = (int)(r % nc);
            int rb = (int)(r / nc);
            int row = rb*128 + mt*16 + (lane >> 2);
            int k   = ci*32 + ks*16 + (lane & 3)*2;
            float v[8];
            int rows2[2] = {row, row + 8};
            int cols2[2] = {k, k + 8};
#pragma unroll
            for (int rI = 0; rI < 2; rI++)
#pragma unroll
                for (int cI = 0; cI < 2; cI++)
#pragma unroll
                    for (int h2 = 0; h2 < 2; h2++) {
                        int kk = cols2[cI] + h2;
                        float val = 0.0f;
                        if (kk < K1) {
                            size_t o = (size_t)rows2[rI]*K1 + kk;
                            val = A1[o];
                            if (A1b) val += A1b[o];
                            if (A1c) val += A1c[o];
                        } else if (kk < K) {
                            val = A2[(size_t)rows2[rI]*K2 + (kk - K1)];
                        }
                        v[cI*4 + rI*2 + h2] = val;
                    }
            uint4 hi, lo;
            float t0, t1;
            t0 = __bfloat162float(__float2bfloat16(v[0])); t1 = __bfloat162float(__float2bfloat16(v[1]));
            hi.x = pack_bf2(v[0], v[1]); lo.x = pack_bf2(v[0]-t0, v[1]-t1);
            t0 = __bfloat162float(__float2bfloat16(v[2])); t1 = __bfloat162float(__float2bfloat16(v[3]));
            hi.y = pack_bf2(v[2], v[3]); lo.y = pack_bf2(v[2]-t0, v[3]-t1);
            t0 = __bfloat162float(__float2bfloat16(v[4])); t1 = __bfloat162float(__float2bfloat16(v[5]));
            hi.z = pack_bf2(v[4], v[5]); lo.z = pack_bf2(v[4]-t0, v[5]-t1);
            t0 = __bfloat162float(__float2bfloat16(v[6])); t1 = __bfloat162float(__float2bfloat16(v[7]));
            hi.w = pack_bf2(v[6], v[7]); lo.w = pack_bf2(v[6]-t0, v[7]-t1);
            size_t base = ((size_t)rb*nc + ci)*1024;
            int entry = (ks*8 + mt)*32 + lane;
            g_Afrag[base + entry*2    ] = hi;
            g_Afrag[base + entry*2 + 1] = lo;
        } else {
            size_t idx = gidx - aTotal;
            int lane  = (int)(idx & 31);
            int ntile = (int)((idx >> 5) & 15);
            int ks    = (int)((idx >> 9) & 1);
            size_t r  = idx >> 10;
            int ci = (int)(r % nc);
            int nbk = (int)(r / nc);
            int n = nbk*128 + ntile*8 + (lane >> 2);
            int k = ci*32 + ks*16 + (lane & 3)*2;
            float v0=0.f, v1=0.f, v2=0.f, v3=0.f;
            if (n < N) {
                if (k   < K) v0 = W[(size_t)n*K + k];
                if (k+1 < K) v1 = W[(size_t)n*K + k+1];
                if (k+8 < K) v2 = W[(size_t)n*K + k+8];
                if (k+9 < K) v3 = W[(size_t)n*K + k+9];
            }
            float h0 = __bfloat162float(__float2bfloat16(v0));
            float h1 = __bfloat162float(__float2bfloat16(v1));
            float h2 = __bfloat162float(__float2bfloat16(v2));
            float h3 = __bfloat162float(__float2bfloat16(v3));
            uint4 o;
            o.x = pack_bf2(v0, v1);
            o.y = pack_bf2(v2, v3);
            o.z = pack_bf2(v0 - h0, v1 - h1);
            o.w = pack_bf2(v2 - h2, v3 - h3);
            g_Wfrag2[((size_t)nbk*nc + ci)*1024 + (ks*16 + ntile)*32 + lane] = o;
        }
    }
}

// pack whh into per-lane B fragments (verified)
__global__ void wfrag_prep(const float* __restrict__ whh)
{
    size_t idx = (size_t)blockIdx.x*blockDim.x + threadIdx.x;
    if (idx >= (size_t)128*8*8*3*32) return;
    int lane = (int)(idx & 31);
    size_t r1 = idx >> 5;
    int nt = (int)(r1 % 3);
    size_t r2 = r1 / 3;
    int q = (int)(r2 & 7);
    int w = (int)((r2 >> 3) & 7);
    int c = (int)(r2 >> 6);
    int gid = lane >> 2, tig = lane & 3;
    const float* wp = whh + (size_t)(nt*HH + c*8 + gid)*HH + w*128 + q*16;
    float v0 = wp[2*tig], v1 = wp[2*tig+1], v2 = wp[2*tig+8], v3 = wp[2*tig+9];
    float h0 = __bfloat162float(__float2bfloat16(v0));
    float h1 = __bfloat162float(__float2bfloat16(v1));
    float h2 = __bfloat162float(__float2bfloat16(v2));
    float h3 = __bfloat162float(__float2bfloat16(v3));
    uint4 o;
    o.x = pack_bf2(v0, v1);
    o.y = pack_bf2(v2, v3);
    o.z = pack_bf2(v0 - h0, v1 - h1);
    o.w = pack_bf2(v2 - h2, v3 - h3);
    g_wfrag[idx] = o;
}

__global__ void hfrag_zero()
{
    int i = blockIdx.x*blockDim.x + threadIdx.x;
    if (i < 4*64*64) g_hfrag[i] = make_uint4(0u,0u,0u,0u);
}

// ---------------- mma primitives ----------------
__device__ __forceinline__ void mma16816(float* c,
    uint32_t a0, uint32_t a1, uint32_t a2, uint32_t a3,
    uint32_t b0, uint32_t b1)
{
    asm volatile(
        "mma.sync.aligned.m16n8k16.row.col.f32.bf16.bf16.f32 "
        "{%0,%1,%2,%3}, {%4,%5,%6,%7}, {%8,%9}, {%0,%1,%2,%3};"
        : "+f"(c[0]), "+f"(c[1]), "+f"(c[2]), "+f"(c[3])
        : "r"(a0), "r"(a1), "r"(a2), "r"(a3), "r"(b0), "r"(b1));
}

__device__ __forceinline__ uint32_t smem_u32(const void* p) {
    uint32_t a;
    asm("{ .reg .u64 t; cvta.to.shared.u64 t, %1; cvt.u32.u64 %0, t; }" : "=r"(a) : "l"(p));
    return a;
}
#define CP_ASYNC16(dst, src) \
    asm volatile("cp.async.cg.shared.global [%0], [%1], 16;" :: "r"(dst), "l"(src) : "memory")
#define CP_COMMIT() asm volatile("cp.async.commit_group;" ::: "memory")
#define CP_WAIT(n)  asm volatile("cp.async.wait_group %0;" :: "n"(n) : "memory")

#define LDG_CG_V4(v, p) \
    asm volatile("ld.global.cg.v4.u32 {%0,%1,%2,%3}, [%4];" \
        : "=r"((v).x), "=r"((v).y), "=r"((v).z), "=r"((v).w) : "l"(p))

// ---------------- tensor-core batch GEMM, frag-packed, 3-stage, term-major ----------------
#define STAGE3_B 32768
#define NST3     3
#define GEMM3_SMEM (NST3*STAGE3_B)

__global__ __launch_bounds__(256, 2)
void gemm_mma3(int nc, int N, const float* __restrict__ bias,
               float* __restrict__ C, int doRelu, int outBT)
{
    extern __shared__ char dynsm[];
    const int tid = threadIdx.x;
    const int lane = tid & 31, wid = tid >> 5;
    const int wm = wid >> 1, wn = wid & 1;
    const int row0 = blockIdx.y * 128;
    const int n0   = blockIdx.x * 128;

    const uint4* Asrc = g_Afrag  + (size_t)blockIdx.y*nc*1024;
    const uint4* Wsrc = g_Wfrag2 + (size_t)blockIdx.x*nc*1024;
    const uint32_t sb = smem_u32(dynsm);

    auto issue_stage = [&](int st, int ci) {
        uint32_t dstA = sb + st*STAGE3_B         + tid*16;
        uint32_t dstW = sb + st*STAGE3_B + 16384 + tid*16;
        const uint4* sa = Asrc + (size_t)ci*1024 + tid;
        const uint4* sw = Wsrc + (size_t)ci*1024 + tid;
#pragma unroll
        for (int u = 0; u < 4; u++) {
            CP_ASYNC16(dstA + u*4096, sa + u*256);
            CP_ASYNC16(dstW + u*4096, sw + u*256);
        }
        CP_COMMIT();
    };

    float acc[2][8][4];
#pragma unroll
    for (int mt = 0; mt < 2; mt++)
#pragma unroll
        for (int nt = 0; nt < 8; nt++)
#pragma unroll
            for (int r = 0; r < 4; r++) acc[mt][nt][r] = 0.0f;

    issue_stage(0, 0);
    issue_stage(1, 1);

    int st = 0;
    for (int i = 0; i < nc; i++) {
        if (i == nc - 1) { CP_WAIT(0); } else { CP_WAIT(1); }
        __syncthreads();
        if (i + NST3 - 1 < nc) {
            int ist = st + 2; if (ist >= NST3) ist -= NST3;
            issue_stage(ist, i + NST3 - 1);
        }

        const uint4* sA = (const uint4*)(dynsm + st*STAGE3_B);
        const uint4* sW = (const uint4*)(dynsm + st*STAGE3_B + 16384);

#pragma unroll
        for (int ks = 0; ks < 2; ks++) {
            uint4 ah[2], al[2];
#pragma unroll
            for (int mt = 0; mt < 2; mt++) {
                int entry = (ks*8 + wm*2 + mt)*32 + lane;
                ah[mt] = sA[entry*2];
                al[mt] = sA[entry*2 + 1];
            }
            uint4 bw[8];
#pragma unroll
            for (int nt = 0; nt < 8; nt++)
                bw[nt] = sW[(ks*16 + wn*8 + nt)*32 + lane];
            // term-major ordering: 16 independent MMAs between RAW-dependent ones
#pragma unroll
            for (int nt = 0; nt < 8; nt++)
#pragma unroll
                for (int mt = 0; mt < 2; mt++)
                    mma16816(acc[mt][nt], ah[mt].x, ah[mt].y, ah[mt].z, ah[mt].w, bw[nt].x, bw[nt].y);
#pragma unroll
            for (int nt = 0; nt < 8; nt++)
#pragma unroll
                for (int mt = 0; mt < 2; mt++)
                    mma16816(acc[mt][nt], ah[mt].x, ah[mt].y, ah[mt].z, ah[mt].w, bw[nt].z, bw[nt].w);
#pragma unroll
            for (int nt = 0; nt < 8; nt++)
#pragma unroll
                for (int mt = 0; mt < 2; mt++)
                    mma16816(acc[mt][nt], al[mt].x, al[mt].y, al[mt].z, al[mt].w, bw[nt].x, bw[nt].y);
        }
        if (++st == NST3) st = 0;
    }

    // epilogue (verified mapping)
    const int g = lane >> 2, tg = lane & 3;
#pragma unroll
    for (int mt = 0; mt < 2; mt++) {
        int mrow0 = row0 + wm*32 + mt*16 + g;
#pragma unroll
        for (int nt = 0; nt < 8; nt++) {
            int col = n0 + wn*64 + nt*8 + tg*2;
#pragma unroll
            for (int r = 0; r < 4; r++) {
                int m = mrow0 + (r >> 1)*8;
                int n = col + (r & 1);
                if (n < N) {
                    float v = acc[mt][nt][r] + bias[n];
                    if (doRelu) v = fmaxf(v, 0.0f);
                    if (outBT) {
                        int t = m >> 6, b = m & (BB-1);
                        C[((size_t)b*TD + t)*N + n] = v;
                    } else {
                        C[(size_t)m*N + n] = v;
                    }
                }
            }
        }
    }
}

// ---------------- persistent mma.sync GRU recurrence ----------------
__device__ __forceinline__ float sigmoidf(float x) { return 1.0f/(1.0f + expf(-x)); }

__device__ __forceinline__ void grid_barrier()
{
    __threadfence();
    __syncthreads();
    if (threadIdx.x == 0) {
        unsigned g = *(volatile unsigned*)&g_bargen;
        unsigned old = atomicAdd(&g_barcnt, 1u);
        if (old == GRU_NBLK - 1u) {
            atomicExch(&g_barcnt, 0u);
            __threadfence();
            atomicAdd(&g_bargen, 1u);
        } else {
            while (*(volatile unsigned*)&g_bargen == g) { }
        }
        __threadfence();
    }
    __syncthreads();
}

#define GRU_SMEM3 (98304 + 49152)

__global__ __launch_bounds__(256, 1)
void gru_pass(int pass, const float* __restrict__ bhh)
{
    float* hall = (pass == 0) ? g_h1 : (pass == 1) ? g_h2 : g_h3;
    extern __shared__ char gsm[];
    uint4* wsm  = (uint4*)gsm;
    float* sred = (float*)(gsm + 98304);
    const int tid = threadIdx.x, wid = tid >> 5, lane = tid & 31;
    const int c = blockIdx.x;

    {
        const uint4* src = g_wfrag + (size_t)c*6144;
        for (int i = tid; i < 6144; i += 256) wsm[i] = src[i];
    }
    __syncthreads();

    for (int t = 0; t < TD; t++) {
        const int par = t & 1;
        const uint4* hbase = g_hfrag + (size_t)par*4*64*64;

        float acc[4][3][4];
#pragma unroll
        for (int m = 0; m < 4; m++)
#pragma unroll
            for (int nt = 0; nt < 3; nt++)
#pragma unroll
                for (int r = 0; r < 4; r++) acc[m][nt][r] = 0.0f;

#pragma unroll 2
        for (int q = 0; q < 8; q++) {
            const int s = wid*8 + q;
            uint4 ah[4], al[4];
#pragma unroll
            for (int m = 0; m < 4; m++) {
                const uint4* p = hbase + ((size_t)m*64 + s)*64 + lane*2;
                LDG_CG_V4(ah[m], p);        // L2-only: cross-CTA ping-pong, L1 unsafe
                LDG_CG_V4(al[m], p + 1);
            }
            uint4 bw[3];
#pragma unroll
            for (int nt = 0; nt < 3; nt++)
                bw[nt] = wsm[((wid*8 + q)*3 + nt)*32 + lane];
            // term-major ordering
#pragma unroll
            for (int m = 0; m < 4; m++)
#pragma unroll
                for (int nt = 0; nt < 3; nt++)
                    mma16816(acc[m][nt], ah[m].x, ah[m].y, ah[m].z, ah[m].w, bw[nt].x, bw[nt].y);
#pragma unroll
            for (int m = 0; m < 4; m++)
#pragma unroll
                for (int nt = 0; nt < 3; nt++)
                    mma16816(acc[m][nt], ah[m].x, ah[m].y, ah[m].z, ah[m].w, bw[nt].z, bw[nt].w);
#pragma unroll
            for (int m = 0; m < 4; m++)
#pragma unroll
                for (int nt = 0; nt < 3; nt++)
                    mma16816(acc[m][nt], al[m].x, al[m].y, al[m].z, al[m].w, bw[nt].x, bw[nt].y);
        }
#pragma unroll
        for (int m = 0; m < 4; m++)
#pragma unroll
            for (int nt = 0; nt < 3; nt++)
#pragma unroll
                for (int r = 0; r < 4; r++)
                    sred[(((wid*4 + m)*3 + nt)*4 + r)*32 + lane] = acc[m][nt][r];
        __syncthreads();

        const int par2 = (t + 1) & 1;
        for (int o = tid; o < 512; o += 256) {
            int b = o >> 3, j = o & 7;
            int jg = c*8 + j;
            int m = b >> 4;
            int rowhi = (b >> 3) & 1;
            int lo_ = (b & 7)*4 + (j >> 1);
            int rc = rowhi*2 + (j & 1);
            float gsum[3];
#pragma unroll
            for (int nt = 0; nt < 3; nt++) {
                float s_ = 0.0f;
#pragma unroll
                for (int w = 0; w < 8; w++)
                    s_ += sred[(((w*4 + m)*3 + nt)*4 + rc)*32 + lo_];
                gsum[nt] = s_;
            }
            const float* gib = g_gi + ((size_t)t*BB + b)*3*HH;
            float rr = sigmoidf(gib[jg]        + gsum[0] + bhh[jg]);
            float zz = sigmoidf(gib[HH + jg]   + gsum[1] + bhh[HH + jg]);
            float nn = tanhf   (gib[2*HH + jg] + rr*(gsum[2] + bhh[2*HH + jg]));
            float hp = (t > 0) ? hall[((size_t)(t-1)*BB + b)*HH + jg] : 0.0f;
            float h  = (1.0f - zz)*nn + zz*hp;
            hall[((size_t)t*BB + b)*HH + jg] = h;

            __nv_bfloat16 hhi = __float2bfloat16(h);
            __nv_bfloat16 hlo = __float2bfloat16(h - __bfloat162float(hhi));
            int s = jg >> 4;
            int colhi = c & 1;
            int reg = rowhi + 2*colhi;
            uint8_t* base = (uint8_t*)g_hfrag
                + (((size_t)par2*4 + m)*64 + s)*1024 + lo_*32;
            *(__nv_bfloat16*)(base + reg*4 + (j & 1)*2)      = hhi;
            *(__nv_bfloat16*)(base + 16 + reg*4 + (j & 1)*2) = hlo;
        }
        grid_barrier();
    }
}

// ---------------- host orchestration ----------------
extern "C" void kernel_launch(void* const* d_in, const int* in_sizes, int n_in,
                              void* d_out, int out_size)
{
    const float* memorys = (const float*)d_in[0];
    const float* dec     = (const float*)d_in[1];
    const float* pre_w1 = (const float*)d_in[3];
    const float* pre_b1 = (const float*)d_in[4];
    const float* pre_w2 = (const float*)d_in[5];
    const float* pre_b2 = (const float*)d_in[6];
    const float* g1_wih = (const float*)d_in[7];
    const float* g1_whh = (const float*)d_in[8];
    const float* g1_bih = (const float*)d_in[9];
    const float* g1_bhh = (const float*)d_in[10];
    const float* att_w  = (const float*)d_in[11];
    const float* att_b  = (const float*)d_in[12];
    const float* g2_wih = (const float*)d_in[13];
    const float* g2_whh = (const float*)d_in[14];
    const float* g2_bih = (const float*)d_in[15];
    const float* g2_bhh = (const float*)d_in[16];
    const float* g3_wih = (const float*)d_in[17];
    const float* g3_whh = (const float*)d_in[18];
    const float* g3_bih = (const float*)d_in[19];
    const float* g3_bhh = (const float*)d_in[20];
    const float* proj_w = (const float*)d_in[21];
    const float* proj_b = (const float*)d_in[22];
    float* out = (float*)d_out;

    float *p_di,*p_mem,*p_xa,*p_xb,*p_gi,*p_h1,*p_h2,*p_h3,*p_d2;
    cudaGetSymbolAddress((void**)&p_di,  g_di);
    cudaGetSymbolAddress((void**)&p_mem, g_mem);
    cudaGetSymbolAddress((void**)&p_xa,  g_xa);
    cudaGetSymbolAddress((void**)&p_xb,  g_xb);
    cudaGetSymbolAddress((void**)&p_gi,  g_gi);
    cudaGetSymbolAddress((void**)&p_h1,  g_h1);
    cudaGetSymbolAddress((void**)&p_h2,  g_h2);
    cudaGetSymbolAddress((void**)&p_h3,  g_h3);
    cudaGetSymbolAddress((void**)&p_d2,  g_d2);

    cudaFuncSetAttribute(gemm_mma3, cudaFuncAttributeMaxDynamicSharedMemorySize, GEMM3_SMEM);
    cudaFuncSetAttribute(gru_pass,  cudaFuncAttributeMaxDynamicSharedMemorySize, GRU_SMEM3);

    pool_kernel<<<4096, 256>>>(memorys);
    di_kernel  <<<4096, 256>>>(dec);

    // prep + gemm: A = (A1 [+A1b] [+A1c]) concat A2
    auto gemm = [&](const float* A1, const float* A1b, const float* A1c, int K1,
                    const float* A2, int K2,
                    const float* W, const float* b, float* C, int N,
                    int relu, int bt) {
        int K = K1 + K2;
        int Kce = (K + 31) & ~31;
        int Nce = (N + 127) & ~127;
        int nc = Kce / 32;
        int nb = Nce / 128;
        prep_gemm<<<8192, 256>>>(A1, A1b, A1c, K1, A2, K2, W, N, nb, nc);
        dim3 grid(nb, NRB);
        gemm_mma3<<<grid, 256, GEMM3_SMEM>>>(nc, N, b, C, relu, bt);
    };

    // prenet
    gemm(p_di, nullptr, nullptr, MMI, nullptr, 0, pre_w1, pre_b1, p_xa, PP, 1, 0);
    gemm(p_xa, nullptr, nullptr, PP,  nullptr, 0, pre_w2, pre_b2, p_xb, PP, 1, 0);

    // GRU1
    gemm(p_xb, nullptr, nullptr, PP, p_mem, EE, g1_wih, g1_bih, p_gi, 3*HH, 0, 0);
    wfrag_prep<<<3072, 256>>>(g1_whh);
    hfrag_zero<<<64, 256>>>();
    gru_pass<<<GRU_NBLK, 256, GRU_SMEM3>>>(0, g1_bhh);

    // attention linear + GRU2
    gemm(p_h1, nullptr, nullptr, HH, p_mem, EE, att_w, att_b, p_d2, HH, 0, 0);
    gemm(p_d2, nullptr, nullptr, HH, nullptr, 0, g2_wih, g2_bih, p_gi, 3*HH, 0, 0);
    wfrag_prep<<<3072, 256>>>(g2_whh);
    hfrag_zero<<<64, 256>>>();
    gru_pass<<<GRU_NBLK, 256, GRU_SMEM3>>>(1, g2_bhh);

    // GRU3: A = r2 = h2 + d2 (folded into prep)
    gemm(p_h2, p_d2, nullptr, HH, nullptr, 0, g3_wih, g3_bih, p_gi, 3*HH, 0, 0);
    wfrag_prep<<<3072, 256>>>(g3_whh);
    hfrag_zero<<<64, 256>>>();
    gru_pass<<<GRU_NBLK, 256, GRU_SMEM3>>>(2, g3_bhh);

    // projection: A = r3 = h3 + h2 + d2 (folded), concat mem; out in [B,T,160]
    gemm(p_h3, p_h2, p_d2, HH, p_mem, EE, proj_w, proj_b, out, MMI*2, 0, 1);
}

// round 14
// speedup vs baseline: 1.0089x; 1.0089x over previous
#include <cuda_runtime.h>
#include <cuda_bf16.h>
#include <math.h>
#include <stdint.h>

#define BB   64
#define TMEL 2000
#define EE   512
#define MMI  80
#define PP   256
#define HH   1024
#define TD   1000
#define RR   (TD*BB)

#define GRU_NBLK 128
#define NRB      (RR/128)      // 500 row blocks

// ---------------- static device scratch (allocation-free rule) ----------------
__device__ float g_di [(size_t)RR*MMI];
__device__ float g_mem[(size_t)RR*EE];
__device__ float g_xa [(size_t)RR*PP];
__device__ float g_xb [(size_t)RR*PP];
__device__ float g_gi [(size_t)RR*3*HH];
__device__ float g_h1 [(size_t)RR*HH];
__device__ float g_h2 [(size_t)RR*HH];
__device__ float g_h3 [(size_t)RR*HH];
__device__ float g_d2 [(size_t)RR*HH];

// fragment-packed GEMM operands
__device__ __align__(16) uint4 g_Afrag[(size_t)NRB*48*1024];
__device__ __align__(16) uint4 g_Wfrag2[(size_t)24*48*1024];

// mma-fragment-packed recurrent weights + h ping-pong (verified)
__device__ __align__(16) uint4 g_wfrag[(size_t)128*8*8*3*32];
__device__ __align__(16) uint4 g_hfrag[(size_t)2*4*64*64];

__device__ unsigned g_barcnt;
__device__ unsigned g_bargen;

// ---------------- small prep kernels ----------------
__global__ void pool_kernel(const float* __restrict__ memorys)
{
    size_t total = (size_t)RR * EE;
    for (size_t i = (size_t)blockIdx.x*blockDim.x + threadIdx.x; i < total;
         i += (size_t)gridDim.x*blockDim.x) {
        int e = (int)(i % EE);
        int tb = (int)(i / EE);
        int b = tb & (BB-1);
        int t = tb >> 6;
        const float* src = memorys + ((size_t)b*TMEL + 2*t)*EE + e;
        g_mem[i] = 0.5f*(src[0] + src[EE]);
    }
}

__global__ void di_kernel(const float* __restrict__ dec)
{
    size_t total = (size_t)RR * MMI;
    for (size_t i = (size_t)blockIdx.x*blockDim.x + threadIdx.x; i < total;
         i += (size_t)gridDim.x*blockDim.x) {
        int m = (int)(i % MMI);
        int tb = (int)(i / MMI);
        int b = tb & (BB-1);
        int t = tb >> 6;
        g_di[i] = (t == 0) ? 0.0f : dec[((size_t)b*TMEL + (2*t-1))*MMI + m];
    }
}

__device__ __forceinline__ uint32_t pack_bf2(float lo, float hi)
{
    __nv_bfloat162 t = __floats2bfloat162_rn(lo, hi);
    return *(uint32_t*)&t;
}

// fused GEMM prep: A-frag pack (with optional multi-source add) + W-frag pack
__global__ void prep_gemm(const float* __restrict__ A1,
                          const float* __restrict__ A1b,
                          const float* __restrict__ A1c, int K1,
                          const float* __restrict__ A2, int K2,
                          const float* __restrict__ W, int N, int nb, int nc)
{
    const int K = K1 + K2;
    const size_t aTotal = (size_t)NRB * nc * 512;
    const size_t wTotal = (size_t)nb * nc * 1024;
    for (size_t gidx = (size_t)blockIdx.x*blockDim.x + threadIdx.x;
         gidx < aTotal + wTotal;
         gidx += (size_t)gridDim.x*blockDim.x) {
        if (gidx < aTotal) {
            size_t idx = gidx;
            int lane = (int)(idx & 31);
            int mt   = (int)((idx >> 5) & 7);
            int ks   = (int)((idx >> 8) & 1);
            size_t r = idx >> 9;
            int ci = (int)(r % nc);
            int rb = (int)(r / nc);
            int row = rb*128 + mt*16 + (lane >> 2);
            int k   = ci*32 + ks*16 + (lane & 3)*2;
            float v[8];
            int rows2[2] = {row, row + 8};
            int cols2[2] = {k, k + 8};
#pragma unroll
            for (int rI = 0; rI < 2; rI++)
#pragma unroll
                for (int cI = 0; cI < 2; cI++)
#pragma unroll
                    for (int h2 = 0; h2 < 2; h2++) {
                        int kk = cols2[cI] + h2;
                        float val = 0.0f;
                        if (kk < K1) {
                            size_t o = (size_t)rows2[rI]*K1 + kk;
                            val = A1[o];
                            if (A1b) val += A1b[o];
                            if (A1c) val += A1c[o];
                        } else if (kk < K) {
                            val = A2[(size_t)rows2[rI]*K2 + (kk - K1)];
                        }
                        v[cI*4 + rI*2 + h2] = val;
                    }
            uint4 hi, lo;
            float t0, t1;
            t0 = __bfloat162float(__float2bfloat16(v[0])); t1 = __bfloat162float(__float2bfloat16(v[1]));
            hi.x = pack_bf2(v[0], v[1]); lo.x = pack_bf2(v[0]-t0, v[1]-t1);
            t0 = __bfloat162float(__float2bfloat16(v[2])); t1 = __bfloat162float(__float2bfloat16(v[3]));
            hi.y = pack_bf2(v[2], v[3]); lo.y = pack_bf2(v[2]-t0, v[3]-t1);
            t0 = __bfloat162float(__float2bfloat16(v[4])); t1 = __bfloat162float(__float2bfloat16(v[5]));
            hi.z = pack_bf2(v[4], v[5]); lo.z = pack_bf2(v[4]-t0, v[5]-t1);
            t0 = __bfloat162float(__float2bfloat16(v[6])); t1 = __bfloat162float(__float2bfloat16(v[7]));
            hi.w = pack_bf2(v[6], v[7]); lo.w = pack_bf2(v[6]-t0, v[7]-t1);
            size_t base = ((size_t)rb*nc + ci)*1024;
            int entry = (ks*8 + mt)*32 + lane;
            g_Afrag[base + entry*2    ] = hi;
            g_Afrag[base + entry*2 + 1] = lo;
        } else {
            size_t idx = gidx - aTotal;
            int lane  = (int)(idx & 31);
            int ntile = (int)((idx >> 5) & 15);
            int ks    = (int)((idx >> 9) & 1);
            size_t r  = idx >> 10;
            int ci = (int)(r % nc);
            int nbk = (int)(r / nc);
            int n = nbk*128 + ntile*8 + (lane >> 2);
            int k = ci*32 + ks*16 + (lane & 3)*2;
            float v0=0.f, v1=0.f, v2=0.f, v3=0.f;
            if (n < N) {
                if (k   < K) v0 = W[(size_t)n*K + k];
                if (k+1 < K) v1 = W[(size_t)n*K + k+1];
                if (k+8 < K) v2 = W[(size_t)n*K + k+8];
                if (k+9 < K) v3 = W[(size_t)n*K + k+9];
            }
            float h0 = __bfloat162float(__float2bfloat16(v0));
            float h1 = __bfloat162float(__float2bfloat16(v1));
            float h2 = __bfloat162float(__float2bfloat16(v2));
            float h3 = __bfloat162float(__float2bfloat16(v3));
            uint4 o;
            o.x = pack_bf2(v0, v1);
            o.y = pack_bf2(v2, v3);
            o.z = pack_bf2(v0 - h0, v1 - h1);
            o.w = pack_bf2(v2 - h2, v3 - h3);
            g_Wfrag2[((size_t)nbk*nc + ci)*1024 + (ks*16 + ntile)*32 + lane] = o;
        }
    }
}

// pack whh into per-lane B fragments (verified)
__global__ void wfrag_prep(const float* __restrict__ whh)
{
    size_t idx = (size_t)blockIdx.x*blockDim.x + threadIdx.x;
    if (idx >= (size_t)128*8*8*3*32) return;
    int lane = (int)(idx & 31);
    size_t r1 = idx >> 5;
    int nt = (int)(r1 % 3);
    size_t r2 = r1 / 3;
    int q = (int)(r2 & 7);
    int w = (int)((r2 >> 3) & 7);
    int c = (int)(r2 >> 6);
    int gid = lane >> 2, tig = lane & 3;
    const float* wp = whh + (size_t)(nt*HH + c*8 + gid)*HH + w*128 + q*16;
    float v0 = wp[2*tig], v1 = wp[2*tig+1], v2 = wp[2*tig+8], v3 = wp[2*tig+9];
    float h0 = __bfloat162float(__float2bfloat16(v0));
    float h1 = __bfloat162float(__float2bfloat16(v1));
    float h2 = __bfloat162float(__float2bfloat16(v2));
    float h3 = __bfloat162float(__float2bfloat16(v3));
    uint4 o;
    o.x = pack_bf2(v0, v1);
    o.y = pack_bf2(v2, v3);
    o.z = pack_bf2(v0 - h0, v1 - h1);
    o.w = pack_bf2(v2 - h2, v3 - h3);
    g_wfrag[idx] = o;
}

__global__ void hfrag_zero()
{
    int i = blockIdx.x*blockDim.x + threadIdx.x;
    if (i < 4*64*64) g_hfrag[i] = make_uint4(0u,0u,0u,0u);
}

// ---------------- mma primitives ----------------
__device__ __forceinline__ void mma16816(float* c,
    uint32_t a0, uint32_t a1, uint32_t a2, uint32_t a3,
    uint32_t b0, uint32_t b1)
{
    asm volatile(
        "mma.sync.aligned.m16n8k16.row.col.f32.bf16.bf16.f32 "
        "{%0,%1,%2,%3}, {%4,%5,%6,%7}, {%8,%9}, {%0,%1,%2,%3};"
        : "+f"(c[0]), "+f"(c[1]), "+f"(c[2]), "+f"(c[3])
        : "r"(a0), "r"(a1), "r"(a2), "r"(a3), "r"(b0), "r"(b1));
}

__device__ __forceinline__ uint32_t smem_u32(const void* p) {
    uint32_t a;
    asm("{ .reg .u64 t; cvta.to.shared.u64 t, %1; cvt.u32.u64 %0, t; }" : "=r"(a) : "l"(p));
    return a;
}
#define CP_ASYNC16(dst, src) \
    asm volatile("cp.async.cg.shared.global [%0], [%1], 16;" :: "r"(dst), "l"(src) : "memory")
#define CP_COMMIT() asm volatile("cp.async.commit_group;" ::: "memory")
#define CP_WAIT(n)  asm volatile("cp.async.wait_group %0;" :: "n"(n) : "memory")

#define LDG_CG_V4(v, p) \
    asm volatile("ld.global.cg.v4.u32 {%0,%1,%2,%3}, [%4];" \
        : "=r"((v).x), "=r"((v).y), "=r"((v).z), "=r"((v).w) : "l"(p))

// ---------------- tensor-core batch GEMM, frag-packed, 3-stage, nt-pair ordering ----------------
#define STAGE3_B 32768
#define NST3     3
#define GEMM3_SMEM (NST3*STAGE3_B)

__global__ __launch_bounds__(256, 2)
void gemm_mma3(int nc, int N, const float* __restrict__ bias,
               float* __restrict__ C, int doRelu, int outBT)
{
    extern __shared__ char dynsm[];
    const int tid = threadIdx.x;
    const int lane = tid & 31, wid = tid >> 5;
    const int wm = wid >> 1, wn = wid & 1;
    const int row0 = blockIdx.y * 128;
    const int n0   = blockIdx.x * 128;

    const uint4* Asrc = g_Afrag  + (size_t)blockIdx.y*nc*1024;
    const uint4* Wsrc = g_Wfrag2 + (size_t)blockIdx.x*nc*1024;
    const uint32_t sb = smem_u32(dynsm);

    auto issue_stage = [&](int st, int ci) {
        uint32_t dstA = sb + st*STAGE3_B         + tid*16;
        uint32_t dstW = sb + st*STAGE3_B + 16384 + tid*16;
        const uint4* sa = Asrc + (size_t)ci*1024 + tid;
        const uint4* sw = Wsrc + (size_t)ci*1024 + tid;
#pragma unroll
        for (int u = 0; u < 4; u++) {
            CP_ASYNC16(dstA + u*4096, sa + u*256);
            CP_ASYNC16(dstW + u*4096, sw + u*256);
        }
        CP_COMMIT();
    };

    float acc[2][8][4];
#pragma unroll
    for (int mt = 0; mt < 2; mt++)
#pragma unroll
        for (int nt = 0; nt < 8; nt++)
#pragma unroll
            for (int r = 0; r < 4; r++) acc[mt][nt][r] = 0.0f;

    issue_stage(0, 0);
    issue_stage(1, 1);

    int st = 0;
    for (int i = 0; i < nc; i++) {
        if (i == nc - 1) { CP_WAIT(0); } else { CP_WAIT(1); }
        __syncthreads();
        if (i + NST3 - 1 < nc) {
            int ist = st + 2; if (ist >= NST3) ist -= NST3;
            issue_stage(ist, i + NST3 - 1);
        }

        const uint4* sA = (const uint4*)(dynsm + st*STAGE3_B);
        const uint4* sW = (const uint4*)(dynsm + st*STAGE3_B + 16384);

#pragma unroll
        for (int ks = 0; ks < 2; ks++) {
            uint4 ah[2], al[2];
#pragma unroll
            for (int mt = 0; mt < 2; mt++) {
                int entry = (ks*8 + wm*2 + mt)*32 + lane;
                ah[mt] = sA[entry*2];
                al[mt] = sA[entry*2 + 1];
            }
            // nt-pair term-major: RAW distance 4, only 2 bw frags live
#pragma unroll
            for (int np = 0; np < 4; np++) {
                uint4 bw0 = sW[(ks*16 + wn*8 + 2*np    )*32 + lane];
                uint4 bw1 = sW[(ks*16 + wn*8 + 2*np + 1)*32 + lane];
                float* a00 = acc[0][2*np];
                float* a10 = acc[1][2*np];
                float* a01 = acc[0][2*np + 1];
                float* a11 = acc[1][2*np + 1];
                // term 1: hi * bh
                mma16816(a00, ah[0].x, ah[0].y, ah[0].z, ah[0].w, bw0.x, bw0.y);
                mma16816(a10, ah[1].x, ah[1].y, ah[1].z, ah[1].w, bw0.x, bw0.y);
                mma16816(a01, ah[0].x, ah[0].y, ah[0].z, ah[0].w, bw1.x, bw1.y);
                mma16816(a11, ah[1].x, ah[1].y, ah[1].z, ah[1].w, bw1.x, bw1.y);
                // term 2: hi * bl
                mma16816(a00, ah[0].x, ah[0].y, ah[0].z, ah[0].w, bw0.z, bw0.w);
                mma16816(a10, ah[1].x, ah[1].y, ah[1].z, ah[1].w, bw0.z, bw0.w);
                mma16816(a01, ah[0].x, ah[0].y, ah[0].z, ah[0].w, bw1.z, bw1.w);
                mma16816(a11, ah[1].x, ah[1].y, ah[1].z, ah[1].w, bw1.z, bw1.w);
                // term 3: lo * bh
                mma16816(a00, al[0].x, al[0].y, al[0].z, al[0].w, bw0.x, bw0.y);
                mma16816(a10, al[1].x, al[1].y, al[1].z, al[1].w, bw0.x, bw0.y);
                mma16816(a01, al[0].x, al[0].y, al[0].z, al[0].w, bw1.x, bw1.y);
                mma16816(a11, al[1].x, al[1].y, al[1].z, al[1].w, bw1.x, bw1.y);
            }
        }
        if (++st == NST3) st = 0;
    }

    // epilogue (verified mapping)
    const int g = lane >> 2, tg = lane & 3;
#pragma unroll
    for (int mt = 0; mt < 2; mt++) {
        int mrow0 = row0 + wm*32 + mt*16 + g;
#pragma unroll
        for (int nt = 0; nt < 8; nt++) {
            int col = n0 + wn*64 + nt*8 + tg*2;
#pragma unroll
            for (int r = 0; r < 4; r++) {
                int m = mrow0 + (r >> 1)*8;
                int n = col + (r & 1);
                if (n < N) {
                    float v = acc[mt][nt][r] + bias[n];
                    if (doRelu) v = fmaxf(v, 0.0f);
                    if (outBT) {
                        int t = m >> 6, b = m & (BB-1);
                        C[((size_t)b*TD + t)*N + n] = v;
                    } else {
                        C[(size_t)m*N + n] = v;
                    }
                }
            }
        }
    }
}

// ---------------- persistent mma.sync GRU recurrence ----------------
__device__ __forceinline__ float sigmoidf(float x) { return 1.0f/(1.0f + expf(-x)); }

__device__ __forceinline__ void grid_barrier()
{
    __threadfence();
    __syncthreads();
    if (threadIdx.x == 0) {
        unsigned g = *(volatile unsigned*)&g_bargen;
        unsigned old = atomicAdd(&g_barcnt, 1u);
        if (old == GRU_NBLK - 1u) {
            atomicExch(&g_barcnt, 0u);
            __threadfence();
            atomicAdd(&g_bargen, 1u);
        } else {
            while (*(volatile unsigned*)&g_bargen == g) { }
        }
        __threadfence();
    }
    __syncthreads();
}

#define GRU_SMEM3 (98304 + 49152)

__global__ __launch_bounds__(256, 1)
void gru_pass(int pass, const float* __restrict__ bhh)
{
    float* hall = (pass == 0) ? g_h1 : (pass == 1) ? g_h2 : g_h3;
    extern __shared__ char gsm[];
    uint4* wsm  = (uint4*)gsm;
    float* sred = (float*)(gsm + 98304);
    const int tid = threadIdx.x, wid = tid >> 5, lane = tid & 31;
    const int c = blockIdx.x;

    {
        const uint4* src = g_wfrag + (size_t)c*6144;
        for (int i = tid; i < 6144; i += 256) wsm[i] = src[i];
    }
    __syncthreads();

    for (int t = 0; t < TD; t++) {
        const int par = t & 1;
        const uint4* hbase = g_hfrag + (size_t)par*4*64*64;

        float acc[4][3][4];
#pragma unroll
        for (int m = 0; m < 4; m++)
#pragma unroll
            for (int nt = 0; nt < 3; nt++)
#pragma unroll
                for (int r = 0; r < 4; r++) acc[m][nt][r] = 0.0f;

#pragma unroll 2
        for (int q = 0; q < 8; q++) {
            const int s = wid*8 + q;
            uint4 ah[4], al[4];
#pragma unroll
            for (int m = 0; m < 4; m++) {
                const uint4* p = hbase + ((size_t)m*64 + s)*64 + lane*2;
                LDG_CG_V4(ah[m], p);        // L2-only: cross-CTA ping-pong, L1 unsafe
                LDG_CG_V4(al[m], p + 1);
            }
            uint4 bw[3];
#pragma unroll
            for (int nt = 0; nt < 3; nt++)
                bw[nt] = wsm[((wid*8 + q)*3 + nt)*32 + lane];
            // term-major ordering (RAW distance 12; no reg pressure at occ 1)
#pragma unroll
            for (int m = 0; m < 4; m++)
#pragma unroll
                for (int nt = 0; nt < 3; nt++)
                    mma16816(acc[m][nt], ah[m].x, ah[m].y, ah[m].z, ah[m].w, bw[nt].x, bw[nt].y);
#pragma unroll
            for (int m = 0; m < 4; m++)
#pragma unroll
                for (int nt = 0; nt < 3; nt++)
                    mma16816(acc[m][nt], ah[m].x, ah[m].y, ah[m].z, ah[m].w, bw[nt].z, bw[nt].w);
#pragma unroll
            for (int m = 0; m < 4; m++)
#pragma unroll
                for (int nt = 0; nt < 3; nt++)
                    mma16816(acc[m][nt], al[m].x, al[m].y, al[m].z, al[m].w, bw[nt].x, bw[nt].y);
        }
#pragma unroll
        for (int m = 0; m < 4; m++)
#pragma unroll
            for (int nt = 0; nt < 3; nt++)
#pragma unroll
                for (int r = 0; r < 4; r++)
                    sred[(((wid*4 + m)*3 + nt)*4 + r)*32 + lane] = acc[m][nt][r];
        __syncthreads();

        const int par2 = (t + 1) & 1;
        for (int o = tid; o < 512; o += 256) {
            int b = o >> 3, j = o & 7;
            int jg = c*8 + j;
            int m = b >> 4;
            int rowhi = (b >> 3) & 1;
            int lo_ = (b & 7)*4 + (j >> 1);
            int rc = rowhi*2 + (j & 1);
            float gsum[3];
#pragma unroll
            for (int nt = 0; nt < 3; nt++) {
                float s_ = 0.0f;
#pragma unroll
                for (int w = 0; w < 8; w++)
                    s_ += sred[(((w*4 + m)*3 + nt)*4 + rc)*32 + lo_];
                gsum[nt] = s_;
            }
            const float* gib = g_gi + ((size_t)t*BB + b)*3*HH;
            float rr = sigmoidf(gib[jg]        + gsum[0] + bhh[jg]);
            float zz = sigmoidf(gib[HH + jg]   + gsum[1] + bhh[HH + jg]);
            float nn = tanhf   (gib[2*HH + jg] + rr*(gsum[2] + bhh[2*HH + jg]));
            float hp = (t > 0) ? hall[((size_t)(t-1)*BB + b)*HH + jg] : 0.0f;
            float h  = (1.0f - zz)*nn + zz*hp;
            hall[((size_t)t*BB + b)*HH + jg] = h;

            __nv_bfloat16 hhi = __float2bfloat16(h);
            __nv_bfloat16 hlo = __float2bfloat16(h - __bfloat162float(hhi));
            int s = jg >> 4;
            int colhi = c & 1;
            int reg = rowhi + 2*colhi;
            uint8_t* base = (uint8_t*)g_hfrag
                + (((size_t)par2*4 + m)*64 + s)*1024 + lo_*32;
            *(__nv_bfloat16*)(base + reg*4 + (j & 1)*2)      = hhi;
            *(__nv_bfloat16*)(base + 16 + reg*4 + (j & 1)*2) = hlo;
        }
        grid_barrier();
    }
}

// ---------------- host orchestration ----------------
extern "C" void kernel_launch(void* const* d_in, const int* in_sizes, int n_in,
                              void* d_out, int out_size)
{
    const float* memorys = (const float*)d_in[0];
    const float* dec     = (const float*)d_in[1];
    const float* pre_w1 = (const float*)d_in[3];
    const float* pre_b1 = (const float*)d_in[4];
    const float* pre_w2 = (const float*)d_in[5];
    const float* pre_b2 = (const float*)d_in[6];
    const float* g1_wih = (const float*)d_in[7];
    const float* g1_whh = (const float*)d_in[8];
    const float* g1_bih = (const float*)d_in[9];
    const float* g1_bhh = (const float*)d_in[10];
    const float* att_w  = (const float*)d_in[11];
    const float* att_b  = (const float*)d_in[12];
    const float* g2_wih = (const float*)d_in[13];
    const float* g2_whh = (const float*)d_in[14];
    const float* g2_bih = (const float*)d_in[15];
    const float* g2_bhh = (const float*)d_in[16];
    const float* g3_wih = (const float*)d_in[17];
    const float* g3_whh = (const float*)d_in[18];
    const float* g3_bih = (const float*)d_in[19];
    const float* g3_bhh = (const float*)d_in[20];
    const float* proj_w = (const float*)d_in[21];
    const float* proj_b = (const float*)d_in[22];
    float* out = (float*)d_out;

    float *p_di,*p_mem,*p_xa,*p_xb,*p_gi,*p_h1,*p_h2,*p_h3,*p_d2;
    cudaGetSymbolAddress((void**)&p_di,  g_di);
    cudaGetSymbolAddress((void**)&p_mem, g_mem);
    cudaGetSymbolAddress((void**)&p_xa,  g_xa);
    cudaGetSymbolAddress((void**)&p_xb,  g_xb);
    cudaGetSymbolAddress((void**)&p_gi,  g_gi);
    cudaGetSymbolAddress((void**)&p_h1,  g_h1);
    cudaGetSymbolAddress((void**)&p_h2,  g_h2);
    cudaGetSymbolAddress((void**)&p_h3,  g_h3);
    cudaGetSymbolAddress((void**)&p_d2,  g_d2);

    cudaFuncSetAttribute(gemm_mma3, cudaFuncAttributeMaxDynamicSharedMemorySize, GEMM3_SMEM);
    cudaFuncSetAttribute(gru_pass,  cudaFuncAttributeMaxDynamicSharedMemorySize, GRU_SMEM3);

    pool_kernel<<<4096, 256>>>(memorys);
    di_kernel  <<<4096, 256>>>(dec);

    // prep + gemm: A = (A1 [+A1b] [+A1c]) concat A2
    auto gemm = [&](const float* A1, const float* A1b, const float* A1c, int K1,
                    const float* A2, int K2,
                    const float* W, const float* b, float* C, int N,
                    int relu, int bt) {
        int K = K1 + K2;
        int Kce = (K + 31) & ~31;
        int Nce = (N + 127) & ~127;
        int nc = Kce / 32;
        int nb = Nce / 128;
        prep_gemm<<<8192, 256>>>(A1, A1b, A1c, K1, A2, K2, W, N, nb, nc);
        dim3 grid(nb, NRB);
        gemm_mma3<<<grid, 256, GEMM3_SMEM>>>(nc, N, b, C, relu, bt);
    };

    // prenet
    gemm(p_di, nullptr, nullptr, MMI, nullptr, 0, pre_w1, pre_b1, p_xa, PP, 1, 0);
    gemm(p_xa, nullptr, nullptr, PP,  nullptr, 0, pre_w2, pre_b2, p_xb, PP, 1, 0);

    // GRU1
    gemm(p_xb, nullptr, nullptr, PP, p_mem, EE, g1_wih, g1_bih, p_gi, 3*HH, 0, 0);
    wfrag_prep<<<3072, 256>>>(g1_whh);
    hfrag_zero<<<64, 256>>>();
    gru_pass<<<GRU_NBLK, 256, GRU_SMEM3>>>(0, g1_bhh);

    // attention linear + GRU2
    gemm(p_h1, nullptr, nullptr, HH, p_mem, EE, att_w, att_b, p_d2, HH, 0, 0);
    gemm(p_d2, nullptr, nullptr, HH, nullptr, 0, g2_wih, g2_bih, p_gi, 3*HH, 0, 0);
    wfrag_prep<<<3072, 256>>>(g2_whh);
    hfrag_zero<<<64, 256>>>();
    gru_pass<<<GRU_NBLK, 256, GRU_SMEM3>>>(1, g2_bhh);

    // GRU3: A = r2 = h2 + d2 (folded into prep)
    gemm(p_h2, p_d2, nullptr, HH, nullptr, 0, g3_wih, g3_bih, p_gi, 3*HH, 0, 0);
    wfrag_prep<<<3072, 256>>>(g3_whh);
    hfrag_zero<<<64, 256>>>();
    gru_pass<<<GRU_NBLK, 256, GRU_SMEM3>>>(2, g3_bhh);

    // projection: A = r3 = h3 + h2 + d2 (folded), concat mem; out in [B,T,160]
    gemm(p_h3, p_h2, p_d2, HH, p_mem, EE, proj_w, proj_b, out, MMI*2, 0, 1);
}